// round 1
// baseline (speedup 1.0000x reference)
#include <cuda_runtime.h>
#include <cuda_bf16.h>
#include <math.h>

#define BB 8
#define SS 2048
#define DD 768
#define BSD (BB*SS*DD)
#define BSS (BB*SS*SS)

// Scratch: Q, K, V  (3 * 8*2048*768 floats = 151 MB)
__device__ float g_QKV[3][BSD];

// ---------------------------------------------------------------------------
// GEMM-NT: C[m,n] = alpha * sum_k A[m,k] * B[n,k]
// A: [M,K] row-major (lda), B: [N,K] row-major (ldb), C: [M,N] row-major (ldc)
// Tile 64x64, K-tile 16, 256 threads (16x16), 4x4 per thread.
// ---------------------------------------------------------------------------
__global__ __launch_bounds__(256) void gemm_nt_kernel(
    const float* __restrict__ A, const float* __restrict__ Bm, float* __restrict__ C,
    int K, long long sA, long long sB, long long sC,
    int lda, int ldb, int ldc, float alpha)
{
    A  += blockIdx.z * sA;
    Bm += blockIdx.z * sB;
    C  += blockIdx.z * sC;

    __shared__ float As[16][64];
    __shared__ float Bs[16][64];

    const int tx = threadIdx.x, ty = threadIdx.y;
    const int tid = ty * 16 + tx;
    const int m0 = blockIdx.x * 64;
    const int n0 = blockIdx.y * 64;

    const int lm  = tid >> 2;   // 0..63 row within tile
    const int lk4 = tid & 3;    // 0..3 float4 along K

    float acc[4][4];
#pragma unroll
    for (int i = 0; i < 4; i++)
#pragma unroll
        for (int j = 0; j < 4; j++) acc[i][j] = 0.f;

    for (int k0 = 0; k0 < K; k0 += 16) {
        float4 av = *(const float4*)(A  + (size_t)(m0 + lm) * lda + k0 + lk4 * 4);
        float4 bv = *(const float4*)(Bm + (size_t)(n0 + lm) * ldb + k0 + lk4 * 4);
        As[lk4*4+0][lm] = av.x; As[lk4*4+1][lm] = av.y;
        As[lk4*4+2][lm] = av.z; As[lk4*4+3][lm] = av.w;
        Bs[lk4*4+0][lm] = bv.x; Bs[lk4*4+1][lm] = bv.y;
        Bs[lk4*4+2][lm] = bv.z; Bs[lk4*4+3][lm] = bv.w;
        __syncthreads();

#pragma unroll
        for (int kk = 0; kk < 16; kk++) {
            float4 a = *(const float4*)&As[kk][ty * 4];
            float4 b = *(const float4*)&Bs[kk][tx * 4];
            acc[0][0] += a.x*b.x; acc[0][1] += a.x*b.y; acc[0][2] += a.x*b.z; acc[0][3] += a.x*b.w;
            acc[1][0] += a.y*b.x; acc[1][1] += a.y*b.y; acc[1][2] += a.y*b.z; acc[1][3] += a.y*b.w;
            acc[2][0] += a.z*b.x; acc[2][1] += a.z*b.y; acc[2][2] += a.z*b.z; acc[2][3] += a.z*b.w;
            acc[3][0] += a.w*b.x; acc[3][1] += a.w*b.y; acc[3][2] += a.w*b.z; acc[3][3] += a.w*b.w;
        }
        __syncthreads();
    }

#pragma unroll
    for (int i = 0; i < 4; i++) {
        float4 o = make_float4(alpha*acc[i][0], alpha*acc[i][1], alpha*acc[i][2], alpha*acc[i][3]);
        *(float4*)(C + (size_t)(m0 + ty*4 + i) * ldc + n0 + tx*4) = o;
    }
}

// ---------------------------------------------------------------------------
// GEMM-NN: C[m,n] = alpha * sum_k A[m,k] * B[k,n]
// A: [M,K] row-major (lda), B: [K,N] row-major (ldb), C: [M,N] row-major (ldc)
// ---------------------------------------------------------------------------
__global__ __launch_bounds__(256) void gemm_nn_kernel(
    const float* __restrict__ A, const float* __restrict__ Bm, float* __restrict__ C,
    int K, long long sA, long long sB, long long sC,
    int lda, int ldb, int ldc, float alpha)
{
    A  += blockIdx.z * sA;
    Bm += blockIdx.z * sB;
    C  += blockIdx.z * sC;

    __shared__ float As[16][64];
    __shared__ float Bs[16][64];

    const int tx = threadIdx.x, ty = threadIdx.y;
    const int tid = ty * 16 + tx;
    const int m0 = blockIdx.x * 64;
    const int n0 = blockIdx.y * 64;

    const int lm  = tid >> 2;   // A-tile row
    const int lk4 = tid & 3;    // A-tile float4 along K
    const int lk  = tid >> 4;   // B-tile k row
    const int ln4 = tid & 15;   // B-tile float4 along N

    float acc[4][4];
#pragma unroll
    for (int i = 0; i < 4; i++)
#pragma unroll
        for (int j = 0; j < 4; j++) acc[i][j] = 0.f;

    for (int k0 = 0; k0 < K; k0 += 16) {
        float4 av = *(const float4*)(A + (size_t)(m0 + lm) * lda + k0 + lk4 * 4);
        As[lk4*4+0][lm] = av.x; As[lk4*4+1][lm] = av.y;
        As[lk4*4+2][lm] = av.z; As[lk4*4+3][lm] = av.w;
        float4 bv = *(const float4*)(Bm + (size_t)(k0 + lk) * ldb + n0 + ln4 * 4);
        *(float4*)&Bs[lk][ln4 * 4] = bv;
        __syncthreads();

#pragma unroll
        for (int kk = 0; kk < 16; kk++) {
            float4 a = *(const float4*)&As[kk][ty * 4];
            float4 b = *(const float4*)&Bs[kk][tx * 4];
            acc[0][0] += a.x*b.x; acc[0][1] += a.x*b.y; acc[0][2] += a.x*b.z; acc[0][3] += a.x*b.w;
            acc[1][0] += a.y*b.x; acc[1][1] += a.y*b.y; acc[1][2] += a.y*b.z; acc[1][3] += a.y*b.w;
            acc[2][0] += a.z*b.x; acc[2][1] += a.z*b.y; acc[2][2] += a.z*b.z; acc[2][3] += a.z*b.w;
            acc[3][0] += a.w*b.x; acc[3][1] += a.w*b.y; acc[3][2] += a.w*b.z; acc[3][3] += a.w*b.w;
        }
        __syncthreads();
    }

#pragma unroll
    for (int i = 0; i < 4; i++) {
        float4 o = make_float4(alpha*acc[i][0], alpha*acc[i][1], alpha*acc[i][2], alpha*acc[i][3]);
        *(float4*)(C + (size_t)(m0 + ty*4 + i) * ldc + n0 + tx*4) = o;
    }
}

// ---------------------------------------------------------------------------
// Row softmax, in place. One block per row of 2048, 256 threads, 8 elems/thread.
// ---------------------------------------------------------------------------
__global__ __launch_bounds__(256) void softmax_kernel(float* __restrict__ attn)
{
    float* p = attn + (size_t)blockIdx.x * SS;
    const int t = threadIdx.x;
    __shared__ float red[256];

    float v[8];
    float m = -INFINITY;
#pragma unroll
    for (int i = 0; i < 8; i++) {
        v[i] = p[t + i * 256];
        m = fmaxf(m, v[i]);
    }
    red[t] = m;
    __syncthreads();
#pragma unroll
    for (int s = 128; s > 0; s >>= 1) {
        if (t < s) red[t] = fmaxf(red[t], red[t + s]);
        __syncthreads();
    }
    m = red[0];
    __syncthreads();

    float sum = 0.f;
#pragma unroll
    for (int i = 0; i < 8; i++) {
        v[i] = __expf(v[i] - m);
        sum += v[i];
    }
    red[t] = sum;
    __syncthreads();
#pragma unroll
    for (int s = 128; s > 0; s >>= 1) {
        if (t < s) red[t] += red[t + s];
        __syncthreads();
    }
    float inv = 1.f / red[0];

#pragma unroll
    for (int i = 0; i < 8; i++) p[t + i * 256] = v[i] * inv;
}

// ---------------------------------------------------------------------------
extern "C" void kernel_launch(void* const* d_in, const int* in_sizes, int n_in,
                              void* d_out, int out_size)
{
    const float* x  = (const float*)d_in[0];
    const float* Wq = (const float*)d_in[1];
    const float* Wk = (const float*)d_in[2];
    const float* Wv = (const float*)d_in[3];

    float* out_wv   = (float*)d_out;          // [B,S,D]
    float* out_attn = (float*)d_out + BSD;    // [B,S,S]

    float* qkv_base = nullptr;
    cudaGetSymbolAddress((void**)&qkv_base, g_QKV);
    float* Q = qkv_base;
    float* K = qkv_base + BSD;
    float* V = qkv_base + 2 * (long long)BSD;

    dim3 blk(16, 16);

    // 1) QKV projections: [16384,768] x [768,768]^T  (C = x * W^T)
    {
        dim3 grid(BB * SS / 64, DD / 64, 1);
        gemm_nt_kernel<<<grid, blk>>>(x, Wq, Q, DD, 0, 0, 0, DD, DD, DD, 1.0f);
        gemm_nt_kernel<<<grid, blk>>>(x, Wk, K, DD, 0, 0, 0, DD, DD, DD, 1.0f);
        gemm_nt_kernel<<<grid, blk>>>(x, Wv, V, DD, 0, 0, 0, DD, DD, DD, 1.0f);
    }

    // 2) scores = Q K^T / sqrt(D)  -> attn output region (unnormalized)
    {
        dim3 grid(SS / 64, SS / 64, BB);
        float alpha = rsqrtf((float)DD);
        gemm_nt_kernel<<<grid, blk>>>(Q, K, out_attn, DD,
                                      (long long)SS * DD, (long long)SS * DD,
                                      (long long)SS * SS, DD, DD, SS, alpha);
    }

    // 3) softmax in place on attn region
    softmax_kernel<<<BB * SS, 256>>>(out_attn);

    // 4) weighted = attn @ V
    {
        dim3 grid(SS / 64, DD / 64, BB);
        gemm_nn_kernel<<<grid, blk>>>(out_attn, V, out_wv, SS,
                                      (long long)SS * SS, (long long)SS * DD,
                                      (long long)SS * DD, SS, DD, DD, 1.0f);
    }
}

// round 4
// speedup vs baseline: 7.4356x; 7.4356x over previous
#include <cuda_runtime.h>
#include <cuda_bf16.h>
#include <math.h>
#include <cstdint>

#define BB 8
#define SS 2048
#define DD 768
#define BSD (BB*SS*DD)

// Scratch: Q, K, Vt, x_rounded, W_rounded[3]
__device__ __align__(16) float g_scr[4ll*BSD + 3ll*DD*DD];

// ---------------- helpers ----------------
__device__ __forceinline__ uint32_t smem_u32(const void* p) {
    uint32_t a;
    asm("{ .reg .u64 t; cvta.to.shared.u64 t, %1; cvt.u32.u64 %0, t; }" : "=r"(a) : "l"(p));
    return a;
}
__device__ __forceinline__ float rna_tf32(float v) {
    uint32_t u; asm("cvt.rna.tf32.f32 %0, %1;" : "=r"(u) : "f"(v));
    return __uint_as_float(u);
}
#define CP_ASYNC16(dst, src) asm volatile("cp.async.cg.shared.global [%0], [%1], 16;" :: "r"(dst), "l"(src))
#define CP_COMMIT() asm volatile("cp.async.commit_group;" ::: "memory")
__device__ __forceinline__ void cp_wait(int n) {
    if (n <= 0)      asm volatile("cp.async.wait_group 0;" ::: "memory");
    else if (n == 1) asm volatile("cp.async.wait_group 1;" ::: "memory");
    else             asm volatile("cp.async.wait_group 2;" ::: "memory");
}

__device__ __forceinline__ void mma1688(float* d, const uint32_t* a, const uint32_t* b) {
    asm volatile(
        "mma.sync.aligned.m16n8k8.row.col.f32.tf32.tf32.f32 "
        "{%0,%1,%2,%3}, {%4,%5,%6,%7}, {%8,%9}, {%0,%1,%2,%3};"
        : "+f"(d[0]), "+f"(d[1]), "+f"(d[2]), "+f"(d[3])
        : "r"(a[0]), "r"(a[1]), "r"(a[2]), "r"(a[3]), "r"(b[0]), "r"(b[1]));
}

// ---------------- tiled tf32 GEMM-NT ----------------
// C[m,n] = alpha * sum_k A[m,k]*B[n,k]
// CTA tile 256x128, BK=32, 8 warps (4 M x 2 N), warp tile 64x64.
// mode 0: plain; 1: tf32-rounded store; 2: transposed (Vt) rounded store
#define BLK_M 256
#define BLK_N 128
#define BK 32
#define NBUF 4
#define LDA_S 36
#define STAGE_FLOATS (BLK_M*LDA_S + BLK_N*LDA_S)
#define STAGE_BYTES (STAGE_FLOATS*4)
#define SMEM_TOTAL (NBUF*STAGE_BYTES)
#define EPI_LD 132   // multiple of 4 -> float4-aligned rows (129 caused misaligned address)

__device__ __forceinline__ void load_stage(uint32_t sbase, const float* A, const float* B,
                                           int lda, int ldb, int k0, int tid) {
#pragma unroll
    for (int t = 0; t < 8; t++) {       // A: 256 rows x 8 chunks
        int idx = tid + t * 256;
        int row = idx >> 3, ck = idx & 7;
        CP_ASYNC16(sbase + (uint32_t)(row * LDA_S + ck * 4) * 4,
                   A + (size_t)row * lda + k0 + ck * 4);
    }
    uint32_t bb = sbase + BLK_M * LDA_S * 4;
#pragma unroll
    for (int t = 0; t < 4; t++) {       // B: 128 rows x 8 chunks
        int idx = tid + t * 256;
        int row = idx >> 3, ck = idx & 7;
        CP_ASYNC16(bb + (uint32_t)(row * LDA_S + ck * 4) * 4,
                   B + (size_t)row * ldb + k0 + ck * 4);
    }
}

__global__ void __launch_bounds__(256, 1) gemm_tc(
    const float* __restrict__ A, const float* __restrict__ B, float* __restrict__ C,
    int Ktot, long long strA, long long strB, long long strC,
    int lda, int ldb, int ldc, float alpha, int mode)
{
    extern __shared__ char smem[];
    const uint32_t sb = smem_u32(smem);
    const int tid = threadIdx.x, wid = tid >> 5, lid = tid & 31;
    const int wm = wid & 3, wn = wid >> 2;
    const int m0 = blockIdx.x * BLK_M, n0 = blockIdx.y * BLK_N;

    A += blockIdx.z * strA + (size_t)m0 * lda;
    B += blockIdx.z * strB + (size_t)n0 * ldb;
    C += blockIdx.z * strC;

    float acc[4][8][4];
#pragma unroll
    for (int i = 0; i < 4; i++)
#pragma unroll
        for (int j = 0; j < 8; j++)
#pragma unroll
            for (int k = 0; k < 4; k++) acc[i][j][k] = 0.f;

    const int iters = Ktot / BK;
    load_stage(sb + 0 * STAGE_BYTES, A, B, lda, ldb, 0, tid);  CP_COMMIT();
    load_stage(sb + 1 * STAGE_BYTES, A, B, lda, ldb, BK, tid); CP_COMMIT();

    for (int i = 0; i < iters; i++) {
        if (i + 2 < iters) {
            load_stage(sb + ((i + 2) % NBUF) * STAGE_BYTES, A, B, lda, ldb, (i + 2) * BK, tid);
            CP_COMMIT();
        }
        int nw = iters - 1 - i; if (nw > 2) nw = 2;
        cp_wait(nw);
        __syncthreads();

        const float* As = (const float*)(smem + (i % NBUF) * STAGE_BYTES);
        const float* Bs = As + BLK_M * LDA_S;
        const int rl = lid >> 2, cl = lid & 3;

#pragma unroll
        for (int ks = 0; ks < BK / 8; ks++) {
            uint32_t af[4][4], bf[8][2];
            const int kk = ks * 8 + cl;
#pragma unroll
            for (int mt = 0; mt < 4; mt++) {
                int ra = wm * 64 + mt * 16 + rl;
                af[mt][0] = __float_as_uint(As[ra * LDA_S + kk]);
                af[mt][1] = __float_as_uint(As[(ra + 8) * LDA_S + kk]);
                af[mt][2] = __float_as_uint(As[ra * LDA_S + kk + 4]);
                af[mt][3] = __float_as_uint(As[(ra + 8) * LDA_S + kk + 4]);
            }
#pragma unroll
            for (int nt = 0; nt < 8; nt++) {
                int rb = wn * 64 + nt * 8 + rl;
                bf[nt][0] = __float_as_uint(Bs[rb * LDA_S + kk]);
                bf[nt][1] = __float_as_uint(Bs[rb * LDA_S + kk + 4]);
            }
#pragma unroll
            for (int mt = 0; mt < 4; mt++)
#pragma unroll
                for (int nt = 0; nt < 8; nt++)
                    mma1688(acc[mt][nt], af[mt], bf[nt]);
        }
    }
    __syncthreads();

    // ---- epilogue: regs -> smem (alpha/round) -> gmem ----
    float* epis = (float*)smem;
    const int rl = lid >> 2, cl = lid & 3;
#pragma unroll
    for (int mt = 0; mt < 4; mt++) {
#pragma unroll
        for (int nt = 0; nt < 8; nt++) {
            int r = wm * 64 + mt * 16 + rl;
            int c = wn * 64 + nt * 8 + 2 * cl;
            float v0 = alpha * acc[mt][nt][0], v1 = alpha * acc[mt][nt][1];
            float v2 = alpha * acc[mt][nt][2], v3 = alpha * acc[mt][nt][3];
            if (mode != 0) { v0 = rna_tf32(v0); v1 = rna_tf32(v1); v2 = rna_tf32(v2); v3 = rna_tf32(v3); }
            epis[r * EPI_LD + c] = v0;
            epis[r * EPI_LD + c + 1] = v1;
            epis[(r + 8) * EPI_LD + c] = v2;
            epis[(r + 8) * EPI_LD + c + 1] = v3;
        }
    }
    __syncthreads();

    if (mode != 2) {
#pragma unroll
        for (int it = 0; it < 32; it++) {
            int idx = tid + it * 256;
            int r = idx >> 5, c4 = (idx & 31) * 4;
            float4 v = *(const float4*)(epis + r * EPI_LD + c4);
            *(float4*)(C + (size_t)(m0 + r) * ldc + n0 + c4) = v;
        }
    } else {
        // C is Vt[B][D][S]
        const int bb = m0 >> 11, s0 = m0 & 2047;
        float* T = C + (size_t)bb * DD * SS + s0;
#pragma unroll
        for (int it = 0; it < 128; it++) {
            int idx = tid + it * 256;
            int r = idx & 255, c = idx >> 8;
            T[(size_t)(n0 + c) * SS + r] = epis[r * EPI_LD + c];
        }
    }
}

// ---------------- tf32 rounding pre-pass ----------------
__global__ __launch_bounds__(256) void round_tf32_kernel(const float* __restrict__ in,
                                                         float* __restrict__ out, int n4) {
    int i = blockIdx.x * 256 + threadIdx.x;
    if (i < n4) {
        float4 v = ((const float4*)in)[i];
        v.x = rna_tf32(v.x); v.y = rna_tf32(v.y); v.z = rna_tf32(v.z); v.w = rna_tf32(v.w);
        ((float4*)out)[i] = v;
    }
}

// ---------------- softmax (in place, tf32-rounded output) ----------------
__global__ __launch_bounds__(256) void softmax_kernel(float* __restrict__ attn) {
    float* p = attn + (size_t)blockIdx.x * SS;
    const int t = threadIdx.x;
    __shared__ float red[256];

    float v[8];
    float m = -INFINITY;
#pragma unroll
    for (int i = 0; i < 8; i++) { v[i] = p[t + i * 256]; m = fmaxf(m, v[i]); }
    red[t] = m; __syncthreads();
#pragma unroll
    for (int s = 128; s > 0; s >>= 1) { if (t < s) red[t] = fmaxf(red[t], red[t + s]); __syncthreads(); }
    m = red[0]; __syncthreads();

    float sum = 0.f;
#pragma unroll
    for (int i = 0; i < 8; i++) { v[i] = __expf(v[i] - m); sum += v[i]; }
    red[t] = sum; __syncthreads();
#pragma unroll
    for (int s = 128; s > 0; s >>= 1) { if (t < s) red[t] += red[t + s]; __syncthreads(); }
    float inv = 1.f / red[0];

#pragma unroll
    for (int i = 0; i < 8; i++) p[t + i * 256] = rna_tf32(v[i] * inv);
}

// ---------------- launcher ----------------
extern "C" void kernel_launch(void* const* d_in, const int* in_sizes, int n_in,
                              void* d_out, int out_size)
{
    const float* x  = (const float*)d_in[0];
    const float* Wq = (const float*)d_in[1];
    const float* Wk = (const float*)d_in[2];
    const float* Wv = (const float*)d_in[3];

    float* out_wv   = (float*)d_out;
    float* out_attn = (float*)d_out + BSD;

    float* base = nullptr;
    cudaGetSymbolAddress((void**)&base, g_scr);
    float* Q   = base;
    float* Km  = base + (long long)BSD;
    float* Vt  = base + 2ll * BSD;
    float* xr  = base + 3ll * BSD;
    float* Wr  = base + 4ll * BSD;

    static int smem_set = 0;
    if (!smem_set) {
        cudaFuncSetAttribute(gemm_tc, cudaFuncAttributeMaxDynamicSharedMemorySize, SMEM_TOTAL);
        smem_set = 1;
    }

    // 0) round inputs to tf32 so MMA products are exact
    round_tf32_kernel<<<(BSD / 4 + 255) / 256, 256>>>(x, xr, BSD / 4);
    round_tf32_kernel<<<(DD * DD / 4 + 255) / 256, 256>>>(Wq, Wr,               DD * DD / 4);
    round_tf32_kernel<<<(DD * DD / 4 + 255) / 256, 256>>>(Wk, Wr + DD * DD,     DD * DD / 4);
    round_tf32_kernel<<<(DD * DD / 4 + 255) / 256, 256>>>(Wv, Wr + 2 * DD * DD, DD * DD / 4);

    // 1) QKV projections (NT): Q/K rounded, V -> transposed rounded Vt
    {
        dim3 grid(BB * SS / BLK_M, DD / BLK_N, 1);
        gemm_tc<<<grid, 256, SMEM_TOTAL>>>(xr, Wr,               Q,  DD, 0, 0, 0, DD, DD, DD, 1.0f, 1);
        gemm_tc<<<grid, 256, SMEM_TOTAL>>>(xr, Wr + DD * DD,     Km, DD, 0, 0, 0, DD, DD, DD, 1.0f, 1);
        gemm_tc<<<grid, 256, SMEM_TOTAL>>>(xr, Wr + 2 * DD * DD, Vt, DD, 0, 0, 0, DD, DD, DD, 1.0f, 2);
    }

    // 2) scores = Q K^T / sqrt(D) -> attn (unnormalized)
    {
        dim3 grid(SS / BLK_M, SS / BLK_N, BB);
        gemm_tc<<<grid, 256, SMEM_TOTAL>>>(Q, Km, out_attn, DD,
                                           (long long)SS * DD, (long long)SS * DD, (long long)SS * SS,
                                           DD, DD, SS, 1.0f / sqrtf((float)DD), 0);
    }

    // 3) softmax (tf32-rounded weights)
    softmax_kernel<<<BB * SS, 256>>>(out_attn);

    // 4) weighted = attn @ V (NT against Vt)
    {
        dim3 grid(SS / BLK_M, DD / BLK_N, BB);
        gemm_tc<<<grid, 256, SMEM_TOTAL>>>(out_attn, Vt, out_wv, SS,
                                           (long long)SS * SS, (long long)DD * SS, (long long)SS * DD,
                                           SS, SS, DD, 1.0f, 0);
    }
}